// round 1
// baseline (speedup 1.0000x reference)
#include <cuda_runtime.h>
#include <math.h>

#define NN 40000
#define NE 640000
#define DIM 128
#define NH 8
#define DH 16

// ---------------- scratch (device globals: allocation-free) ----------------
__device__ float g_Qh[(size_t)NN * DIM];
__device__ float g_Kh[(size_t)NN * DIM];
__device__ float g_Vh[(size_t)NN * DIM];
__device__ float g_Ee[(size_t)NE * 2 * DIM];
__device__ float g_et[(size_t)NE * DIM];
__device__ float g_lg[(size_t)NE * NH];
__device__ float g_mx[(size_t)NN * NH];
__device__ float g_den[(size_t)NN * NH];
__device__ float g_wV[(size_t)NN * DIM];
__device__ float g_rowV[(size_t)NN * DIM];
__device__ float g_hatt[(size_t)NN * DIM];
__device__ float g_v1[(size_t)NN * DIM];
__device__ float g_hbn[(size_t)NN * DIM];
__device__ float g_h2a[(size_t)NN * 2 * DIM];
__device__ float g_v2[(size_t)NN * DIM];
__device__ float g_s1[2 * DIM];
__device__ float g_s2[2 * DIM];
__device__ float g_se[2 * DIM];

static inline int cdiv(long long a, long long b) { return (int)((a + b - 1) / b); }

// ---------------- helpers ----------------
__device__ __forceinline__ void atomicMaxF(float* addr, float v) {
    // ordered-int trick, valid for mixed signs with init = -1e30f
    if (v >= 0.f) atomicMax((int*)addr, __float_as_int(v));
    else          atomicMin((unsigned int*)addr, __float_as_uint(v));
}

__global__ void fill_kernel(float* p, float v, int n) {
    int i = blockIdx.x * blockDim.x + threadIdx.x;
    if (i < n) p[i] = v;
}

// ---------------- GEMM: C[M,Ncols] = A[M,K] @ W[K,Ncols] + bias (+res) (relu) ----------------
// 128x128 block tile, 256 threads, 8x8 per thread, k-chunk 16.
template <bool RES, bool RELU>
__global__ void __launch_bounds__(256)
gemm_kernel(const float* __restrict__ A, const float* __restrict__ W,
            const float* __restrict__ bias, const float* __restrict__ res,
            float* __restrict__ C, int M, int Ncols, int K)
{
    __shared__ float As[16][136];
    __shared__ float Ws[16][128];
    const int m0 = blockIdx.x * 128;
    const int n0 = blockIdx.y * 128;
    const int tid = threadIdx.x;
    const int tx = tid & 15, ty = tid >> 4;

    float acc[8][8];
#pragma unroll
    for (int i = 0; i < 8; i++)
#pragma unroll
        for (int j = 0; j < 8; j++) acc[i][j] = 0.f;

    for (int kc = 0; kc < K; kc += 16) {
#pragma unroll
        for (int u = 0; u < 2; u++) {
            int idx = u * 256 + tid;
            // A tile: 128 rows x 16 k  (512 float4)
            int row = idx >> 2, kq = idx & 3;
            float4 v = make_float4(0.f, 0.f, 0.f, 0.f);
            if (m0 + row < M)
                v = *(const float4*)(A + (size_t)(m0 + row) * K + kc + kq * 4);
            As[kq * 4 + 0][row] = v.x;
            As[kq * 4 + 1][row] = v.y;
            As[kq * 4 + 2][row] = v.z;
            As[kq * 4 + 3][row] = v.w;
            // W tile: 16 k x 128 n (512 float4)
            int k = idx >> 5, nq = idx & 31;
            float4 wv = *(const float4*)(W + (size_t)(kc + k) * Ncols + n0 + nq * 4);
            *(float4*)&Ws[k][nq * 4] = wv;
        }
        __syncthreads();
#pragma unroll
        for (int k = 0; k < 16; k++) {
            const float4 a0 = *(const float4*)&As[k][ty * 4];
            const float4 a1 = *(const float4*)&As[k][64 + ty * 4];
            const float4 b0 = *(const float4*)&Ws[k][tx * 4];
            const float4 b1 = *(const float4*)&Ws[k][64 + tx * 4];
            const float ar[8] = {a0.x, a0.y, a0.z, a0.w, a1.x, a1.y, a1.z, a1.w};
            const float br[8] = {b0.x, b0.y, b0.z, b0.w, b1.x, b1.y, b1.z, b1.w};
#pragma unroll
            for (int i = 0; i < 8; i++)
#pragma unroll
                for (int j = 0; j < 8; j++)
                    acc[i][j] = fmaf(ar[i], br[j], acc[i][j]);
        }
        __syncthreads();
    }

#pragma unroll
    for (int i = 0; i < 8; i++) {
        int row = m0 + ((i < 4) ? (ty * 4 + i) : (64 + ty * 4 + i - 4));
        if (row >= M) continue;
#pragma unroll
        for (int jb = 0; jb < 2; jb++) {
            int col = n0 + jb * 64 + tx * 4;
            float o0 = acc[i][jb * 4 + 0] + bias[col + 0];
            float o1 = acc[i][jb * 4 + 1] + bias[col + 1];
            float o2 = acc[i][jb * 4 + 2] + bias[col + 2];
            float o3 = acc[i][jb * 4 + 3] + bias[col + 3];
            if (RES) {
                float4 r = *(const float4*)(res + (size_t)row * Ncols + col);
                o0 += r.x; o1 += r.y; o2 += r.z; o3 += r.w;
            }
            if (RELU) {
                o0 = fmaxf(o0, 0.f); o1 = fmaxf(o1, 0.f);
                o2 = fmaxf(o2, 0.f); o3 = fmaxf(o3, 0.f);
            }
            float4 o = make_float4(o0, o1, o2, o3);
            *(float4*)(C + (size_t)row * Ncols + col) = o;
        }
    }
}

// ---------------- edge kernels ----------------
union U16 { float4 q[4]; float f[16]; };

__global__ void edge_pass1(const int* __restrict__ ei, const float* __restrict__ Aw,
                           float* __restrict__ et, float* __restrict__ lg,
                           float* __restrict__ mx,
                           const float* __restrict__ Qh, const float* __restrict__ Kh,
                           const float* __restrict__ Ee)
{
    __shared__ float sAw[DIM];
    if (threadIdx.x < DIM) sAw[threadIdx.x] = Aw[threadIdx.x];
    __syncthreads();
    int t = blockIdx.x * blockDim.x + threadIdx.x;
    if (t >= NE * NH) return;
    int e = t >> 3, h = t & 7;
    int src = ei[e], dst = ei[NE + e];

    U16 K4, Q4, Wn, Bn, ET;
    const float4* kp = (const float4*)(Kh + (size_t)src * DIM + h * DH);
    const float4* qp = (const float4*)(Qh + (size_t)dst * DIM + h * DH);
    const float4* wp = (const float4*)(Ee + (size_t)e * (2 * DIM) + h * (2 * DH));
#pragma unroll
    for (int q = 0; q < 4; q++) {
        K4.q[q] = kp[q]; Q4.q[q] = qp[q];
        Wn.q[q] = wp[q]; Bn.q[q] = wp[q + 4];
    }
    float logit = 0.f;
#pragma unroll
    for (int d = 0; d < 16; d++) {
        float s = (K4.f[d] + Q4.f[d]) * Wn.f[d];
        float a = fabsf(s);
        float r = (a > 0.f) ? copysignf(sqrtf(a), s) : 0.f;
        float v = fmaxf(r + Bn.f[d], 0.f);
        ET.f[d] = v;
        logit = fmaf(v, sAw[d * NH + h], logit);
    }
    logit = fminf(fmaxf(logit, -5.f), 5.f);
    float4* ep = (float4*)(et + (size_t)e * DIM + h * DH);
#pragma unroll
    for (int q = 0; q < 4; q++) ep[q] = ET.q[q];
    lg[t] = logit;
    atomicMaxF(&mx[dst * NH + h], logit);
}

__global__ void edge_pass2(const int* __restrict__ ei, float* __restrict__ lg,
                           const float* __restrict__ mx, float* __restrict__ den)
{
    int t = blockIdx.x * blockDim.x + threadIdx.x;
    if (t >= NE * NH) return;
    int e = t >> 3, h = t & 7;
    int dst = ei[NE + e];
    float ex = expf(lg[t] - mx[dst * NH + h]);
    lg[t] = ex;
    atomicAdd(&den[dst * NH + h], ex);
}

__global__ void edge_pass3(const int* __restrict__ ei, const float* __restrict__ lg,
                           const float* __restrict__ den,
                           const float* __restrict__ Vh, const float* __restrict__ et,
                           float* __restrict__ wV, float* __restrict__ rowV)
{
    int t = blockIdx.x * blockDim.x + threadIdx.x;
    if (t >= NE * NH) return;
    int e = t >> 3, h = t & 7;
    int src = ei[e], dst = ei[NE + e];
    float attn = lg[t] / (den[dst * NH + h] + 1e-16f);
    U16 V4, E4;
    const float4* vp = (const float4*)(Vh + (size_t)src * DIM + h * DH);
    const float4* ep = (const float4*)(et + (size_t)e * DIM + h * DH);
#pragma unroll
    for (int q = 0; q < 4; q++) { V4.q[q] = vp[q]; E4.q[q] = ep[q]; }
    float* wv = wV + (size_t)dst * DIM + h * DH;
    float* rv = rowV + (size_t)dst * DIM + h * DH;
#pragma unroll
    for (int d = 0; d < 16; d++) {
        atomicAdd(&wv[d], V4.f[d] * attn);
        atomicAdd(&rv[d], E4.f[d] * attn);
    }
}

// ---------------- node combine: wV + rowV @ VeRow, degree scaler ----------------
__global__ void node_fix(const float* __restrict__ wV, const float* __restrict__ rowV,
                         const float* __restrict__ VeRow, const float* __restrict__ log_deg,
                         const float* __restrict__ deg_coef, float* __restrict__ hatt)
{
    int t = blockIdx.x * blockDim.x + threadIdx.x;
    if (t >= NN * DIM) return;
    int n = t >> 7, c = t & 127, h = c >> 4, co = c & 15;
    float acc = wV[t];
    const float* rv = rowV + (size_t)n * DIM + h * DH;
#pragma unroll
    for (int d2 = 0; d2 < 16; d2++)
        acc = fmaf(rv[d2], VeRow[d2 * DIM + h * DH + co], acc);
    float ld = log_deg[n];
    hatt[t] = acc * (deg_coef[2 * c] + ld * deg_coef[2 * c + 1]);
}

// ---------------- batch norm ----------------
__global__ void bn_stats(const float* __restrict__ v, int M, float* __restrict__ sums)
{
    int c = threadIdx.x;  // 128 threads
    float s = 0.f, s2 = 0.f;
    for (int r = blockIdx.x; r < M; r += gridDim.x) {
        float x = v[(size_t)r * DIM + c];
        s += x;
        s2 = fmaf(x, x, s2);
    }
    atomicAdd(&sums[c], s);
    atomicAdd(&sums[DIM + c], s2);
}

__global__ void bn_apply(const float* __restrict__ v, float* __restrict__ out, int M,
                         const float* __restrict__ sums,
                         const float* __restrict__ g, const float* __restrict__ b, float invM)
{
    long long total = (long long)M * DIM;
    long long i = (long long)blockIdx.x * blockDim.x + threadIdx.x;
    if (i >= total) return;
    int c = (int)(i & (DIM - 1));
    float m = sums[c] * invM;
    float var = fmaf(-m, m, sums[DIM + c] * invM);
    out[i] = (v[i] - m) * rsqrtf(var + 1e-5f) * g[c] + b[c];
}

// ---------------- launch ----------------
extern "C" void kernel_launch(void* const* d_in, const int* in_sizes, int n_in,
                              void* d_out, int out_size)
{
    const float* x         = (const float*)d_in[0];
    const float* edge_attr = (const float*)d_in[1];
    const int*   ei        = (const int*)d_in[2];
    const float* log_deg   = (const float*)d_in[3];
    const float* Wq = (const float*)d_in[4],  *bq  = (const float*)d_in[5];
    const float* Wk = (const float*)d_in[6],  *bk  = (const float*)d_in[7];
    const float* We = (const float*)d_in[8],  *be  = (const float*)d_in[9];
    const float* Wv = (const float*)d_in[10], *bv  = (const float*)d_in[11];
    const float* Aw = (const float*)d_in[12], *VeRow = (const float*)d_in[13];
    const float* WOh = (const float*)d_in[14], *bOh = (const float*)d_in[15];
    const float* WOe = (const float*)d_in[16], *bOe = (const float*)d_in[17];
    const float* deg_coef = (const float*)d_in[18];
    const float* g1h = (const float*)d_in[19], *b1h = (const float*)d_in[20];
    const float* g1e = (const float*)d_in[21], *b1e = (const float*)d_in[22];
    const float* g2h = (const float*)d_in[23], *b2h = (const float*)d_in[24];
    const float* W1 = (const float*)d_in[25], *b1 = (const float*)d_in[26];
    const float* W2 = (const float*)d_in[27], *b2 = (const float*)d_in[28];

    float *Qh, *Kh, *Vh, *Ee, *et, *lg, *mx, *den, *wV, *rowV, *hatt, *v1, *hbn, *h2a, *v2, *s1, *s2, *se;
    cudaGetSymbolAddress((void**)&Qh, g_Qh);
    cudaGetSymbolAddress((void**)&Kh, g_Kh);
    cudaGetSymbolAddress((void**)&Vh, g_Vh);
    cudaGetSymbolAddress((void**)&Ee, g_Ee);
    cudaGetSymbolAddress((void**)&et, g_et);
    cudaGetSymbolAddress((void**)&lg, g_lg);
    cudaGetSymbolAddress((void**)&mx, g_mx);
    cudaGetSymbolAddress((void**)&den, g_den);
    cudaGetSymbolAddress((void**)&wV, g_wV);
    cudaGetSymbolAddress((void**)&rowV, g_rowV);
    cudaGetSymbolAddress((void**)&hatt, g_hatt);
    cudaGetSymbolAddress((void**)&v1, g_v1);
    cudaGetSymbolAddress((void**)&hbn, g_hbn);
    cudaGetSymbolAddress((void**)&h2a, g_h2a);
    cudaGetSymbolAddress((void**)&v2, g_v2);
    cudaGetSymbolAddress((void**)&s1, g_s1);
    cudaGetSymbolAddress((void**)&s2, g_s2);
    cudaGetSymbolAddress((void**)&se, g_se);

    float* hout = (float*)d_out;                       // (N, D)
    float* eout = (float*)d_out + (size_t)NN * DIM;    // (E, D)

    // init accumulators
    cudaMemsetAsync(wV, 0, (size_t)NN * DIM * sizeof(float));
    cudaMemsetAsync(rowV, 0, (size_t)NN * DIM * sizeof(float));
    cudaMemsetAsync(den, 0, (size_t)NN * NH * sizeof(float));
    cudaMemsetAsync(s1, 0, 2 * DIM * sizeof(float));
    cudaMemsetAsync(s2, 0, 2 * DIM * sizeof(float));
    cudaMemsetAsync(se, 0, 2 * DIM * sizeof(float));
    fill_kernel<<<cdiv(NN * NH, 256), 256>>>(mx, -1e30f, NN * NH);

    dim3 gN1(cdiv(NN, 128), 1), gN2(cdiv(NN, 128), 2);
    dim3 gE1(cdiv(NE, 128), 1), gE2(cdiv(NE, 128), 2);

    // projections
    gemm_kernel<false, false><<<gN1, 256>>>(x, Wq, bq, nullptr, Qh, NN, 128, 128);
    gemm_kernel<false, false><<<gN1, 256>>>(x, Wk, bk, nullptr, Kh, NN, 128, 128);
    gemm_kernel<false, false><<<gN1, 256>>>(x, Wv, bv, nullptr, Vh, NN, 128, 128);
    gemm_kernel<false, false><<<gE2, 256>>>(edge_attr, We, be, nullptr, Ee, NE, 256, 128);

    // attention (3 edge passes)
    int eth = NE * NH;
    edge_pass1<<<cdiv(eth, 256), 256>>>(ei, Aw, et, lg, mx, Qh, Kh, Ee);
    edge_pass2<<<cdiv(eth, 256), 256>>>(ei, lg, mx, den);
    edge_pass3<<<cdiv(eth, 256), 256>>>(ei, lg, den, Vh, et, wV, rowV);

    // node combine + degree scaler
    node_fix<<<cdiv(NN * DIM, 256), 256>>>(wV, rowV, VeRow, log_deg, deg_coef, hatt);

    // h path: out proj + residual + BN1
    gemm_kernel<true, false><<<gN1, 256>>>(hatt, WOh, bOh, x, v1, NN, 128, 128);
    bn_stats<<<1024, 128>>>(v1, NN, s1);
    bn_apply<<<cdiv((long long)NN * DIM, 256), 256>>>(v1, hbn, NN, s1, g1h, b1h, 1.f / NN);

    // e path: out proj + residual + BN (written directly into output)
    gemm_kernel<true, false><<<gE1, 256>>>(et, WOe, bOe, edge_attr, eout, NE, 128, 128);
    bn_stats<<<4096, 128>>>(eout, NE, se);
    bn_apply<<<cdiv((long long)NE * DIM, 256), 256>>>(eout, eout, NE, se, g1e, b1e, 1.f / NE);

    // FFN + BN2
    gemm_kernel<false, true><<<gN2, 256>>>(hbn, W1, b1, nullptr, h2a, NN, 256, 128);
    gemm_kernel<true, false><<<gN1, 256>>>(h2a, W2, b2, hbn, v2, NN, 128, 256);
    bn_stats<<<1024, 128>>>(v2, NN, s2);
    bn_apply<<<cdiv((long long)NN * DIM, 256), 256>>>(v2, hout, NN, s2, g2h, b2h, 1.f / NN);
}

// round 3
// speedup vs baseline: 1.2846x; 1.2846x over previous
#include <cuda_runtime.h>
#include <cuda_bf16.h>
#include <math.h>
#include <stdint.h>

#define NN 40000
#define NE 640000
#define DIM 128
#define NH 8
#define DH 16

// ---------------- scratch (device globals: allocation-free) ----------------
__device__ float g_Qh[(size_t)NN * DIM];
__device__ float g_Kh[(size_t)NN * DIM];
__device__ float g_Vh[(size_t)NN * DIM];
__device__ float g_Ee[(size_t)NE * 2 * DIM];
__device__ float g_et[(size_t)NE * DIM];
__device__ float g_lg[(size_t)NE * NH];
__device__ float g_mx[(size_t)NN * NH];
__device__ float g_den[(size_t)NN * NH];
__device__ float g_wV[(size_t)NN * DIM];
__device__ float g_rowV[(size_t)NN * DIM];
__device__ float g_hatt[(size_t)NN * DIM];
__device__ float g_v1[(size_t)NN * DIM];
__device__ float g_hbn[(size_t)NN * DIM];
__device__ float g_h2a[(size_t)NN * 2 * DIM];
__device__ float g_v2[(size_t)NN * DIM];
__device__ float g_s1[2 * DIM];
__device__ float g_s2[2 * DIM];
__device__ float g_se[2 * DIM];

static inline int cdiv(long long a, long long b) { return (int)((a + b - 1) / b); }

// ---------------- mma helpers (plain sm_80+ features: OK on sm_103 non-'a') --
__device__ __forceinline__ uint32_t smem_u32(const void* p) {
    uint32_t a;
    asm("{ .reg .u64 t; cvta.to.shared.u64 t, %1; cvt.u32.u64 %0, t; }" : "=r"(a) : "l"(p));
    return a;
}
__device__ __forceinline__ void ldsm4(uint32_t (&r)[4], uint32_t addr) {
    asm volatile("ldmatrix.sync.aligned.m8n8.x4.shared.b16 {%0,%1,%2,%3}, [%4];"
                 : "=r"(r[0]), "=r"(r[1]), "=r"(r[2]), "=r"(r[3]) : "r"(addr));
}
__device__ __forceinline__ void ldsm2t(uint32_t (&r)[2], uint32_t addr) {
    asm volatile("ldmatrix.sync.aligned.m8n8.x2.trans.shared.b16 {%0,%1}, [%2];"
                 : "=r"(r[0]), "=r"(r[1]) : "r"(addr));
}
__device__ __forceinline__ void mma16816(float (&d)[4], const uint32_t (&a)[4], const uint32_t (&b)[2]) {
    asm volatile("mma.sync.aligned.m16n8k16.row.col.f32.bf16.bf16.f32 "
                 "{%0,%1,%2,%3}, {%4,%5,%6,%7}, {%8,%9}, {%0,%1,%2,%3};"
                 : "+f"(d[0]), "+f"(d[1]), "+f"(d[2]), "+f"(d[3])
                 : "r"(a[0]), "r"(a[1]), "r"(a[2]), "r"(a[3]), "r"(b[0]), "r"(b[1]));
}
__device__ __forceinline__ uint32_t pack2(__nv_bfloat16 a, __nv_bfloat16 b) {
    return (uint32_t)__bfloat16_as_ushort(a) | ((uint32_t)__bfloat16_as_ushort(b) << 16);
}
__device__ __forceinline__ void split4(float4 v, uint2& hi, uint2& lo) {
    __nv_bfloat16 hx = __float2bfloat16(v.x), hy = __float2bfloat16(v.y);
    __nv_bfloat16 hz = __float2bfloat16(v.z), hw = __float2bfloat16(v.w);
    hi = make_uint2(pack2(hx, hy), pack2(hz, hw));
    lo = make_uint2(pack2(__float2bfloat16(v.x - __bfloat162float(hx)),
                          __float2bfloat16(v.y - __bfloat162float(hy))),
                    pack2(__float2bfloat16(v.z - __bfloat162float(hz)),
                          __float2bfloat16(v.w - __bfloat162float(hw))));
}

// ---------------- HMMA GEMM: C[M,Ncols] = A[M,K] @ W[K,Ncols] + bias (+res)(relu)
// bf16 hi/lo compensated split (3 mma products) ~ fp32 precision.
// 128x128 block tile (grid.y covers Ncols>128), 256 thr, warp grid 2m x 4n.
#define KC 32
#define A_PITCH 40   /* bf16 elems: 80B row, 5x16B chunks, conflict-free ldsm */
#define B_PITCH 136  /* bf16 elems: 272B row, 17x16B chunks */
#define SA_HI 0
#define SA_LO (128 * A_PITCH * 2)
#define SB_HI (2 * 128 * A_PITCH * 2)
#define SB_LO (SB_HI + KC * B_PITCH * 2)
#define SM_TOT (SB_LO + KC * B_PITCH * 2)

template <bool RES, bool RELU>
__global__ void __launch_bounds__(256, 2)
mma_gemm(const float* __restrict__ A, const float* __restrict__ W,
         const float* __restrict__ bias, const float* __restrict__ res,
         float* __restrict__ C, int M, int Ncols, int K)
{
    __shared__ __align__(16) uint8_t sm[SM_TOT];
    const uint32_t sb = smem_u32(sm);
    const int tid = threadIdx.x, wid = tid >> 5, lid = tid & 31;
    const int m0 = blockIdx.x * 128, n0 = blockIdx.y * 128;
    const int wm = wid >> 2, wn = wid & 3;   // warp tile: 64m x 32n

    float acc[4][4][4];
#pragma unroll
    for (int i = 0; i < 4; i++)
#pragma unroll
        for (int j = 0; j < 4; j++)
#pragma unroll
            for (int q = 0; q < 4; q++) acc[i][j][q] = 0.f;

    // A-load mapping: row = tid/2, half = tid&1 covers k [half*16, half*16+16)
    const int ar = tid >> 1, ah = tid & 1;
    // B-load mapping: n4 = (tid&31)*4, kk = tid>>5 (+8 per iter)
    const int bn4 = (lid) * 4, bk = wid;

    for (int kb = 0; kb < K; kb += KC) {
        // ---- stage A chunk: 128 rows x 32 k ----
        {
            const bool ok = (m0 + ar) < M;
            const float4* ap = (const float4*)(A + (size_t)(ok ? m0 + ar : 0) * K + kb + ah * 16);
            const uint32_t base = (uint32_t)ar * (A_PITCH * 2) + (uint32_t)ah * 32;
#pragma unroll
            for (int j = 0; j < 4; j++) {
                float4 v = ok ? ap[j] : make_float4(0.f, 0.f, 0.f, 0.f);
                uint2 hi, lo;
                split4(v, hi, lo);
                *(uint2*)(sm + SA_HI + base + j * 8) = hi;
                *(uint2*)(sm + SA_LO + base + j * 8) = lo;
            }
        }
        // ---- stage B chunk: Bs[k][n] = W[kb+k][n0+n], 32 k x 128 n ----
        {
#pragma unroll
            for (int i = 0; i < 4; i++) {
                int k = bk + i * 8;
                float4 v = *(const float4*)(W + (size_t)(kb + k) * Ncols + n0 + bn4);
                uint2 hi, lo;
                split4(v, hi, lo);
                uint32_t off = (uint32_t)k * (B_PITCH * 2) + (uint32_t)bn4 * 2;
                *(uint2*)(sm + SB_HI + off) = hi;
                *(uint2*)(sm + SB_LO + off) = lo;
            }
        }
        __syncthreads();

#pragma unroll
        for (int ks = 0; ks < KC; ks += 16) {
            // B fragments for this warp's 4 n-tiles (hi & lo)
            uint32_t bhi[4][2], blo[4][2];
            const uint32_t brow = (uint32_t)(ks + (lid & 15)) * (B_PITCH * 2);
#pragma unroll
            for (int nt = 0; nt < 4; nt++) {
                uint32_t baddr = sb + brow + (uint32_t)(wn * 32 + nt * 8) * 2;
                ldsm2t(bhi[nt], SB_HI + baddr);
                ldsm2t(blo[nt], SB_LO + baddr);
            }
            const uint32_t arow = (uint32_t)(wm * 64 + (lid & 15)) * (A_PITCH * 2)
                                + (uint32_t)ks * 2 + (uint32_t)(lid >> 4) * 16;
#pragma unroll
            for (int mt = 0; mt < 4; mt++) {
                uint32_t aaddr = sb + arow + (uint32_t)mt * (16 * A_PITCH * 2);
                uint32_t ahi4[4], alo4[4];
                ldsm4(ahi4, SA_HI + aaddr);
                ldsm4(alo4, SA_LO + aaddr);
#pragma unroll
                for (int nt = 0; nt < 4; nt++) {
                    mma16816(acc[mt][nt], ahi4, bhi[nt]);
                    mma16816(acc[mt][nt], ahi4, blo[nt]);
                    mma16816(acc[mt][nt], alo4, bhi[nt]);
                }
            }
        }
        __syncthreads();
    }

    // ---- epilogue ----
    const int qr = lid >> 2, qc = (lid & 3) * 2;
#pragma unroll
    for (int mt = 0; mt < 4; mt++) {
#pragma unroll
        for (int nt = 0; nt < 4; nt++) {
            int col = n0 + wn * 32 + nt * 8 + qc;
            float b0 = bias[col], b1 = bias[col + 1];
#pragma unroll
            for (int half = 0; half < 2; half++) {
                int row = m0 + wm * 64 + mt * 16 + qr + half * 8;
                if (row >= M) continue;
                float o0 = acc[mt][nt][half * 2 + 0] + b0;
                float o1 = acc[mt][nt][half * 2 + 1] + b1;
                if (RES) {
                    const float2 rr = *(const float2*)(res + (size_t)row * Ncols + col);
                    o0 += rr.x; o1 += rr.y;
                }
                if (RELU) { o0 = fmaxf(o0, 0.f); o1 = fmaxf(o1, 0.f); }
                *(float2*)(C + (size_t)row * Ncols + col) = make_float2(o0, o1);
            }
        }
    }
}

// ---------------- misc ----------------
__device__ __forceinline__ void atomicMaxF(float* addr, float v) {
    if (v >= 0.f) atomicMax((int*)addr, __float_as_int(v));
    else          atomicMin((unsigned int*)addr, __float_as_uint(v));
}

__global__ void fill_kernel(float* p, float v, int n) {
    int i = blockIdx.x * blockDim.x + threadIdx.x;
    if (i < n) p[i] = v;
}

// ---------------- edge kernels ----------------
union U16 { float4 q[4]; float f[16]; };

__global__ void edge_pass1(const int* __restrict__ ei, const float* __restrict__ Aw,
                           float* __restrict__ et, float* __restrict__ lg,
                           float* __restrict__ mx,
                           const float* __restrict__ Qh, const float* __restrict__ Kh,
                           const float* __restrict__ Ee)
{
    __shared__ float sAw[DIM];
    if (threadIdx.x < DIM) sAw[threadIdx.x] = Aw[threadIdx.x];
    __syncthreads();
    int t = blockIdx.x * blockDim.x + threadIdx.x;
    if (t >= NE * NH) return;
    int e = t >> 3, h = t & 7;
    int src = ei[e], dst = ei[NE + e];

    U16 K4, Q4, Wn, Bn, ET;
    const float4* kp = (const float4*)(Kh + (size_t)src * DIM + h * DH);
    const float4* qp = (const float4*)(Qh + (size_t)dst * DIM + h * DH);
    const float4* wp = (const float4*)(Ee + (size_t)e * (2 * DIM) + h * (2 * DH));
#pragma unroll
    for (int q = 0; q < 4; q++) {
        K4.q[q] = kp[q]; Q4.q[q] = qp[q];
        Wn.q[q] = wp[q]; Bn.q[q] = wp[q + 4];
    }
    float logit = 0.f;
#pragma unroll
    for (int d = 0; d < 16; d++) {
        float s = (K4.f[d] + Q4.f[d]) * Wn.f[d];
        float a = fabsf(s);
        float r = (a > 0.f) ? copysignf(sqrtf(a), s) : 0.f;
        float v = fmaxf(r + Bn.f[d], 0.f);
        ET.f[d] = v;
        logit = fmaf(v, sAw[d * NH + h], logit);
    }
    logit = fminf(fmaxf(logit, -5.f), 5.f);
    float4* ep = (float4*)(et + (size_t)e * DIM + h * DH);
#pragma unroll
    for (int q = 0; q < 4; q++) ep[q] = ET.q[q];
    lg[t] = logit;
    atomicMaxF(&mx[dst * NH + h], logit);
}

__global__ void edge_pass2(const int* __restrict__ ei, float* __restrict__ lg,
                           const float* __restrict__ mx, float* __restrict__ den)
{
    int t = blockIdx.x * blockDim.x + threadIdx.x;
    if (t >= NE * NH) return;
    int e = t >> 3, h = t & 7;
    int dst = ei[NE + e];
    float ex = expf(lg[t] - mx[dst * NH + h]);
    lg[t] = ex;
    atomicAdd(&den[dst * NH + h], ex);
}

__global__ void edge_pass3(const int* __restrict__ ei, const float* __restrict__ lg,
                           const float* __restrict__ den,
                           const float* __restrict__ Vh, const float* __restrict__ et,
                           float* __restrict__ wV, float* __restrict__ rowV)
{
    int t = blockIdx.x * blockDim.x + threadIdx.x;
    if (t >= NE * NH) return;
    int e = t >> 3, h = t & 7;
    int src = ei[e], dst = ei[NE + e];
    float attn = lg[t] / (den[dst * NH + h] + 1e-16f);
    U16 V4, E4;
    const float4* vp = (const float4*)(Vh + (size_t)src * DIM + h * DH);
    const float4* ep = (const float4*)(et + (size_t)e * DIM + h * DH);
#pragma unroll
    for (int q = 0; q < 4; q++) { V4.q[q] = vp[q]; E4.q[q] = ep[q]; }
    float* wv = wV + (size_t)dst * DIM + h * DH;
    float* rv = rowV + (size_t)dst * DIM + h * DH;
#pragma unroll
    for (int d = 0; d < 16; d++) {
        atomicAdd(&wv[d], V4.f[d] * attn);
        atomicAdd(&rv[d], E4.f[d] * attn);
    }
}

// ---------------- node combine ----------------
__global__ void node_fix(const float* __restrict__ wV, const float* __restrict__ rowV,
                         const float* __restrict__ VeRow, const float* __restrict__ log_deg,
                         const float* __restrict__ deg_coef, float* __restrict__ hatt)
{
    int t = blockIdx.x * blockDim.x + threadIdx.x;
    if (t >= NN * DIM) return;
    int n = t >> 7, c = t & 127, h = c >> 4, co = c & 15;
    float acc = wV[t];
    const float* rv = rowV + (size_t)n * DIM + h * DH;
#pragma unroll
    for (int d2 = 0; d2 < 16; d2++)
        acc = fmaf(rv[d2], VeRow[d2 * DIM + h * DH + co], acc);
    float ld = log_deg[n];
    hatt[t] = acc * (deg_coef[2 * c] + ld * deg_coef[2 * c + 1]);
}

// ---------------- batch norm ----------------
__global__ void bn_stats(const float* __restrict__ v, int M, float* __restrict__ sums)
{
    int c = threadIdx.x;
    float s = 0.f, s2 = 0.f;
    for (int r = blockIdx.x; r < M; r += gridDim.x) {
        float x = v[(size_t)r * DIM + c];
        s += x;
        s2 = fmaf(x, x, s2);
    }
    atomicAdd(&sums[c], s);
    atomicAdd(&sums[DIM + c], s2);
}

__global__ void bn_apply(const float* __restrict__ v, float* __restrict__ out, int M,
                         const float* __restrict__ sums,
                         const float* __restrict__ g, const float* __restrict__ b, float invM)
{
    long long total = (long long)M * DIM;
    long long i = (long long)blockIdx.x * blockDim.x + threadIdx.x;
    if (i >= total) return;
    int c = (int)(i & (DIM - 1));
    float m = sums[c] * invM;
    float var = fmaf(-m, m, sums[DIM + c] * invM);
    out[i] = (v[i] - m) * rsqrtf(var + 1e-5f) * g[c] + b[c];
}

// ---------------- launch ----------------
extern "C" void kernel_launch(void* const* d_in, const int* in_sizes, int n_in,
                              void* d_out, int out_size)
{
    const float* x         = (const float*)d_in[0];
    const float* edge_attr = (const float*)d_in[1];
    const int*   ei        = (const int*)d_in[2];
    const float* log_deg   = (const float*)d_in[3];
    const float* Wq = (const float*)d_in[4],  *bq  = (const float*)d_in[5];
    const float* Wk = (const float*)d_in[6],  *bk  = (const float*)d_in[7];
    const float* We = (const float*)d_in[8],  *be  = (const float*)d_in[9];
    const float* Wv = (const float*)d_in[10], *bv  = (const float*)d_in[11];
    const float* Aw = (const float*)d_in[12], *VeRow = (const float*)d_in[13];
    const float* WOh = (const float*)d_in[14], *bOh = (const float*)d_in[15];
    const float* WOe = (const float*)d_in[16], *bOe = (const float*)d_in[17];
    const float* deg_coef = (const float*)d_in[18];
    const float* g1h = (const float*)d_in[19], *b1h = (const float*)d_in[20];
    const float* g1e = (const float*)d_in[21], *b1e = (const float*)d_in[22];
    const float* g2h = (const float*)d_in[23], *b2h = (const float*)d_in[24];
    const float* W1 = (const float*)d_in[25], *b1 = (const float*)d_in[26];
    const float* W2 = (const float*)d_in[27], *b2 = (const float*)d_in[28];

    float *Qh, *Kh, *Vh, *Ee, *et, *lg, *mx, *den, *wV, *rowV, *hatt, *v1, *hbn, *h2a, *v2, *s1, *s2, *se;
    cudaGetSymbolAddress((void**)&Qh, g_Qh);
    cudaGetSymbolAddress((void**)&Kh, g_Kh);
    cudaGetSymbolAddress((void**)&Vh, g_Vh);
    cudaGetSymbolAddress((void**)&Ee, g_Ee);
    cudaGetSymbolAddress((void**)&et, g_et);
    cudaGetSymbolAddress((void**)&lg, g_lg);
    cudaGetSymbolAddress((void**)&mx, g_mx);
    cudaGetSymbolAddress((void**)&den, g_den);
    cudaGetSymbolAddress((void**)&wV, g_wV);
    cudaGetSymbolAddress((void**)&rowV, g_rowV);
    cudaGetSymbolAddress((void**)&hatt, g_hatt);
    cudaGetSymbolAddress((void**)&v1, g_v1);
    cudaGetSymbolAddress((void**)&hbn, g_hbn);
    cudaGetSymbolAddress((void**)&h2a, g_h2a);
    cudaGetSymbolAddress((void**)&v2, g_v2);
    cudaGetSymbolAddress((void**)&s1, g_s1);
    cudaGetSymbolAddress((void**)&s2, g_s2);
    cudaGetSymbolAddress((void**)&se, g_se);

    float* hout = (float*)d_out;
    float* eout = (float*)d_out + (size_t)NN * DIM;

    // init accumulators
    cudaMemsetAsync(wV, 0, (size_t)NN * DIM * sizeof(float));
    cudaMemsetAsync(rowV, 0, (size_t)NN * DIM * sizeof(float));
    cudaMemsetAsync(den, 0, (size_t)NN * NH * sizeof(float));
    cudaMemsetAsync(s1, 0, 2 * DIM * sizeof(float));
    cudaMemsetAsync(s2, 0, 2 * DIM * sizeof(float));
    cudaMemsetAsync(se, 0, 2 * DIM * sizeof(float));
    fill_kernel<<<cdiv(NN * NH, 256), 256>>>(mx, -1e30f, NN * NH);

    const int gN = cdiv(NN, 128), gE = cdiv(NE, 128);

    // projections (HMMA bf16 split)
    mma_gemm<false, false><<<dim3(gN, 1), 256>>>(x, Wq, bq, nullptr, Qh, NN, 128, 128);
    mma_gemm<false, false><<<dim3(gN, 1), 256>>>(x, Wk, bk, nullptr, Kh, NN, 128, 128);
    mma_gemm<false, false><<<dim3(gN, 1), 256>>>(x, Wv, bv, nullptr, Vh, NN, 128, 128);
    mma_gemm<false, false><<<dim3(gE, 2), 256>>>(edge_attr, We, be, nullptr, Ee, NE, 256, 128);

    // attention (3 edge passes)
    int eth = NE * NH;
    edge_pass1<<<cdiv(eth, 256), 256>>>(ei, Aw, et, lg, mx, Qh, Kh, Ee);
    edge_pass2<<<cdiv(eth, 256), 256>>>(ei, lg, mx, den);
    edge_pass3<<<cdiv(eth, 256), 256>>>(ei, lg, den, Vh, et, wV, rowV);

    // node combine + degree scaler
    node_fix<<<cdiv(NN * DIM, 256), 256>>>(wV, rowV, VeRow, log_deg, deg_coef, hatt);

    // h path: out proj + residual + BN1
    mma_gemm<true, false><<<dim3(gN, 1), 256>>>(hatt, WOh, bOh, x, v1, NN, 128, 128);
    bn_stats<<<1024, 128>>>(v1, NN, s1);
    bn_apply<<<cdiv((long long)NN * DIM, 256), 256>>>(v1, hbn, NN, s1, g1h, b1h, 1.f / NN);

    // e path: out proj + residual + BN (written into output)
    mma_gemm<true, false><<<dim3(gE, 1), 256>>>(et, WOe, bOe, edge_attr, eout, NE, 128, 128);
    bn_stats<<<4096, 128>>>(eout, NE, se);
    bn_apply<<<cdiv((long long)NE * DIM, 256), 256>>>(eout, eout, NE, se, g1e, b1e, 1.f / NE);

    // FFN + BN2
    mma_gemm<false, true><<<dim3(gN, 2), 256>>>(hbn, W1, b1, nullptr, h2a, NN, 256, 128);
    mma_gemm<true, false><<<dim3(gN, 1), 256>>>(h2a, W2, b2, hbn, v2, NN, 128, 256);
    bn_stats<<<1024, 128>>>(v2, NN, s2);
    bn_apply<<<cdiv((long long)NN * DIM, 256), 256>>>(v2, hout, NN, s2, g2h, b2h, 1.f / NN);
}